// round 10
// baseline (speedup 1.0000x reference)
#include <cuda_runtime.h>
#include <cstdint>

// ---------------- problem constants ----------------
#define Nn 8
#define Cc 16
#define Ll 32
#define Dd 24
#define HW24 576
#define Ff 32
#define OL 30
#define OD 22
#define OE 22

// ---------------- scratch (fragment-baked layouts) ----------------
// g_xt: [n][l][d][s=576][tig=4] float4; slot tig = channels (tig, tig+4, tig+8, tig+12)
__device__ float g_xt[(size_t)Nn * Ll * Dd * HW24 * Cc + 1024];   // pad = 64 rows
// g_w2: [pt=81][nt=4][n=8][tig=4] float4, same channel rule; f = nt*8+n
__device__ float g_w2[9 * 9 * 4 * 8 * 16];

__device__ __forceinline__ uint32_t tf32_rna(float x) {
    uint32_t r;
    asm("cvt.rna.tf32.f32 %0, %1;" : "=r"(r) : "f"(x));
    return r;
}
__device__ __forceinline__ uint4 ldg128(const void* p) {
    return __ldg(reinterpret_cast<const uint4*>(p));   // non-volatile: hoistable
}
__device__ __forceinline__ void pf_l1(const void* p) {
    asm volatile("prefetch.global.L1 [%0];" :: "l"(p));
}
__device__ __forceinline__ void mma_tf32(float* d,
    uint32_t a0, uint32_t a1, uint32_t a2, uint32_t a3,
    uint32_t b0, uint32_t b1)
{
    asm volatile(
        "mma.sync.aligned.m16n8k8.row.col.f32.tf32.tf32.f32 "
        "{%0,%1,%2,%3}, {%4,%5,%6,%7}, {%8,%9}, {%0,%1,%2,%3};"
        : "+f"(d[0]), "+f"(d[1]), "+f"(d[2]), "+f"(d[3])
        : "r"(a0), "r"(a1), "r"(a2), "r"(a3), "r"(b0), "r"(b1));
}

// ---------------- prep ----------------
__global__ __launch_bounds__(256)
void prep_all(const float* __restrict__ x, const float* __restrict__ W) {
    int bid = blockIdx.x;
    if (bid < Nn * Ll * Dd) {
        __shared__ float sx[Cc][HW24 + 1];
        int D = bid % Dd;
        int L = (bid / Dd) % Ll;
        int n = bid / (Dd * Ll);
        for (int i4 = threadIdx.x; i4 < Cc * 144; i4 += 256) {
            int c = i4 / 144, r4 = i4 - c * 144;
            const float4 v = *reinterpret_cast<const float4*>(
                x + ((((size_t)(n * Cc + c) * Ll + L) * Dd + D) * HW24 + r4 * 4));
            sx[c][r4 * 4 + 0] = v.x; sx[c][r4 * 4 + 1] = v.y;
            sx[c][r4 * 4 + 2] = v.z; sx[c][r4 * 4 + 3] = v.w;
        }
        __syncthreads();
        float4* dst = reinterpret_cast<float4*>(g_xt + (size_t)bid * (HW24 * Cc));
        for (int i4 = threadIdx.x; i4 < HW24 * 4; i4 += 256) {
            int s = i4 >> 2, tig = i4 & 3;
            uint4 v;
            v.x = tf32_rna(sx[tig][s]);
            v.y = tf32_rna(sx[tig + 4][s]);
            v.z = tf32_rna(sx[tig + 8][s]);
            v.w = tf32_rna(sx[tig + 12][s]);
            dst[i4] = *reinterpret_cast<float4*>(&v);
        }
    } else {
        for (int i = threadIdx.x; i < 9 * 9 * 4 * 8 * 4; i += 256) {
            int tig = i & 3;
            int nrow = (i >> 2) & 7;
            int nt = (i >> 5) & 3;
            int pt = i >> 7;
            int f = nt * 8 + nrow;
            uint4 v;
            v.x = tf32_rna(W[((size_t)f * Cc + tig) * 81 + pt]);
            v.y = tf32_rna(W[((size_t)f * Cc + tig + 4) * 81 + pt]);
            v.z = tf32_rna(W[((size_t)f * Cc + tig + 8) * 81 + pt]);
            v.w = tf32_rna(W[((size_t)f * Cc + tig + 12) * 81 + pt]);
            reinterpret_cast<uint4*>(g_w2)[i] = v;
        }
    }
}

// ---------------- main kernel: 544 threads (17 warps), direct LDG ----------------
#define STAGE_F (16 * 33)
#define NW 17
#define NT (NW * 32)

__global__ __launch_bounds__(NT, 1)
void conv4d_mma(const float* __restrict__ bias, float* __restrict__ out) {
    __shared__ float stg[NW * STAGE_F];
    __shared__ float sbias[Ff];

    const int tid  = threadIdx.x;
    const int wid  = tid >> 5;          // 0..16
    const int lane = tid & 31;
    const int g    = lane >> 2;
    const int tig  = lane & 3;

    int bid = blockIdx.x;
    const int d = bid % OD;
    const int l = (bid / OD) % OL;
    const int n = bid / (OD * OL);

    if (tid < Ff) sbias[tid] = 3.0f * bias[tid];

    float acc[2][4][4];
#pragma unroll
    for (int mt = 0; mt < 2; mt++)
#pragma unroll
        for (int nt = 0; nt < 4; nt++)
#pragma unroll
            for (int k = 0; k < 4; k++) acc[mt][nt][k] = 0.f;

    // block-level slab base + per-thread offsets
    const char* xblk = reinterpret_cast<const char*>(
        g_xt + ((size_t)((n * Ll + l) * Dd) + d) * (HW24 * Cc));
    const char* xsl = xblk + (size_t)(wid * 32 + g) * 64 + tig * 16;
    const char* wb  = reinterpret_cast<const char*>(g_w2) + g * 64 + tig * 16;

    const bool full = (wid < 16);       // warp 16: only mt=0 is live output

#pragma unroll 1
    for (int p = 0; p < 9; ++p) {
        // prefetch next plane (A: 288 lines, B: 144 lines)
        if (p + 1 < 9) {
            const size_t poff = (size_t)(((p + 1) / 3) * Dd + ((p + 1) % 3)) * (HW24 * 64);
            if (tid < 288) pf_l1(xblk + poff + (size_t)tid * 128);
            else if (tid < 432)
                pf_l1(reinterpret_cast<const char*>(g_w2) + (size_t)(p + 1) * 18432
                      + (size_t)(tid - 288) * 128);
        }

        const char* xp = xsl + (size_t)((p / 3) * Dd + (p % 3)) * (HW24 * 64);
        const char* wp = wb + (size_t)p * 18432;

#pragma unroll
        for (int tap = 0; tap < 9; ++tap) {
            const int off = (tap / 3) * 24 + (tap % 3);
            uint4 bf[4];
#pragma unroll
            for (int nt = 0; nt < 4; nt++)
                bf[nt] = ldg128(wp + tap * 2048 + nt * 512);

            {   // mt = 0
                const uint4 a0 = ldg128(xp + off * 64);
                const uint4 a1 = ldg128(xp + (8 + off) * 64);
#pragma unroll
                for (int nt = 0; nt < 4; nt++) {
                    mma_tf32(acc[0][nt], a0.x, a1.x, a0.y, a1.y, bf[nt].x, bf[nt].y);
                    mma_tf32(acc[0][nt], a0.z, a1.z, a0.w, a1.w, bf[nt].z, bf[nt].w);
                }
            }
            if (full) {   // mt = 1 (uniform per-warp branch)
                const uint4 a0 = ldg128(xp + (16 + off) * 64);
                const uint4 a1 = ldg128(xp + (24 + off) * 64);
#pragma unroll
                for (int nt = 0; nt < 4; nt++) {
                    mma_tf32(acc[1][nt], a0.x, a1.x, a0.y, a1.y, bf[nt].x, bf[nt].y);
                    mma_tf32(acc[1][nt], a0.z, a1.z, a0.w, a1.w, bf[nt].z, bf[nt].w);
                }
            }
        }
    }

    // ---- epilogue: per-warp smem staging for coalesced stores ----
    float* st = stg + wid * STAGE_F;
    const int sl = lane & 15;
    const int fh = lane >> 4;
    const int mtmax = full ? 2 : 1;

#pragma unroll 1
    for (int mt = 0; mt < mtmax; mt++) {
#pragma unroll
        for (int nt = 0; nt < 4; nt++) {
            const int col = nt * 8 + 2 * tig;
            st[g * 33 + col]           = acc[mt][nt][0];
            st[g * 33 + col + 1]       = acc[mt][nt][1];
            st[(g + 8) * 33 + col]     = acc[mt][nt][2];
            st[(g + 8) * 33 + col + 1] = acc[mt][nt][3];
        }
        __syncwarp();
        const int s  = wid * 32 + mt * 16 + sl;
        const int oh = s / 24;
        const int ow = s - oh * 24;
        if (oh < OE && ow < OE) {
            const size_t base = ((((size_t)n * Ff) * OL + l) * OD + d) * (OE * OE)
                                + (size_t)oh * OE + ow;
            const size_t fstr = (size_t)OL * OD * OE * OE;
#pragma unroll
            for (int fp = 0; fp < 16; fp++) {
                const int f = fp * 2 + fh;
                out[base + (size_t)f * fstr] = st[sl * 33 + f] + sbias[f];
            }
        }
        __syncwarp();
    }
}

// ---------------- launch ----------------
extern "C" void kernel_launch(void* const* d_in, const int* in_sizes, int n_in,
                              void* d_out, int out_size) {
    const float* x  = (const float*)d_in[0];
    const float* Wt = (const float*)d_in[1];
    const float* b  = (const float*)d_in[2];
    float* out = (float*)d_out;

    prep_all<<<Nn * Ll * Dd + 1, 256>>>(x, Wt);
    conv4d_mma<<<Nn * OL * OD, NT>>>(b, out);
}

// round 11
// speedup vs baseline: 1.1015x; 1.1015x over previous
#include <cuda_runtime.h>
#include <cstdint>

// ---------------- problem constants ----------------
#define Nn 8
#define Cc 16
#define Ll 32
#define Dd 24
#define HW24 576
#define Ff 32
#define OL 30
#define OD 22
#define OE 22

// ---------------- scratch (fragment-baked layouts) ----------------
// g_xt: [n][l][d][s=576][tig=4] float4; slot tig = channels (tig, tig+4, tig+8, tig+12)
__device__ float g_xt[(size_t)Nn * Ll * Dd * HW24 * Cc + 4096];   // pad >= 64 rows
// g_w2: [pt=81][nt=4][n=8][tig=4] float4, same channel rule; f = nt*8+n
__device__ float g_w2[9 * 9 * 4 * 8 * 16];

__device__ __forceinline__ uint32_t tf32_rna(float x) {
    uint32_t r;
    asm("cvt.rna.tf32.f32 %0, %1;" : "=r"(r) : "f"(x));
    return r;
}
__device__ __forceinline__ uint4 ldg128(const void* p) {
    return __ldg(reinterpret_cast<const uint4*>(p));
}
__device__ __forceinline__ void pf_l1(const void* p) {
    asm volatile("prefetch.global.L1 [%0];" :: "l"(p));
}
__device__ __forceinline__ void mma_tf32(float* d,
    uint32_t a0, uint32_t a1, uint32_t a2, uint32_t a3,
    uint32_t b0, uint32_t b1)
{
    asm volatile(
        "mma.sync.aligned.m16n8k8.row.col.f32.tf32.tf32.f32 "
        "{%0,%1,%2,%3}, {%4,%5,%6,%7}, {%8,%9}, {%0,%1,%2,%3};"
        : "+f"(d[0]), "+f"(d[1]), "+f"(d[2]), "+f"(d[3])
        : "r"(a0), "r"(a1), "r"(a2), "r"(a3), "r"(b0), "r"(b1));
}

// ---------------- prep ----------------
__global__ __launch_bounds__(256)
void prep_all(const float* __restrict__ x, const float* __restrict__ W) {
    int bid = blockIdx.x;
    if (bid < Nn * Ll * Dd) {
        __shared__ float sx[Cc][HW24 + 1];
        int D = bid % Dd;
        int L = (bid / Dd) % Ll;
        int n = bid / (Dd * Ll);
        for (int i4 = threadIdx.x; i4 < Cc * 144; i4 += 256) {
            int c = i4 / 144, r4 = i4 - c * 144;
            const float4 v = *reinterpret_cast<const float4*>(
                x + ((((size_t)(n * Cc + c) * Ll + L) * Dd + D) * HW24 + r4 * 4));
            sx[c][r4 * 4 + 0] = v.x; sx[c][r4 * 4 + 1] = v.y;
            sx[c][r4 * 4 + 2] = v.z; sx[c][r4 * 4 + 3] = v.w;
        }
        __syncthreads();
        float4* dst = reinterpret_cast<float4*>(g_xt + (size_t)bid * (HW24 * Cc));
        for (int i4 = threadIdx.x; i4 < HW24 * 4; i4 += 256) {
            int s = i4 >> 2, tig = i4 & 3;
            uint4 v;
            v.x = tf32_rna(sx[tig][s]);
            v.y = tf32_rna(sx[tig + 4][s]);
            v.z = tf32_rna(sx[tig + 8][s]);
            v.w = tf32_rna(sx[tig + 12][s]);
            dst[i4] = *reinterpret_cast<float4*>(&v);
        }
    } else {
        for (int i = threadIdx.x; i < 9 * 9 * 4 * 8 * 4; i += 256) {
            int tig = i & 3;
            int nrow = (i >> 2) & 7;
            int nt = (i >> 5) & 3;
            int pt = i >> 7;
            int f = nt * 8 + nrow;
            uint4 v;
            v.x = tf32_rna(W[((size_t)f * Cc + tig) * 81 + pt]);
            v.y = tf32_rna(W[((size_t)f * Cc + tig + 4) * 81 + pt]);
            v.z = tf32_rna(W[((size_t)f * Cc + tig + 8) * 81 + pt]);
            v.w = tf32_rna(W[((size_t)f * Cc + tig + 12) * 81 + pt]);
            reinterpret_cast<uint4*>(g_w2)[i] = v;
        }
    }
}

// ---------------- main kernel: 11 warps x m48 (3 m16 tiles), covers rows 0..527 ----------------
#define STAGE_F (16 * 33)
#define NW 11
#define NT (NW * 32)

__global__ __launch_bounds__(NT, 1)
void conv4d_mma(const float* __restrict__ bias, float* __restrict__ out) {
    __shared__ float stg[NW * STAGE_F];
    __shared__ float sbias[Ff];

    const int tid  = threadIdx.x;
    const int wid  = tid >> 5;          // 0..10
    const int lane = tid & 31;
    const int g    = lane >> 2;
    const int tig  = lane & 3;

    int bid = blockIdx.x;
    const int d = bid % OD;
    const int l = (bid / OD) % OL;
    const int n = bid / (OD * OL);

    if (tid < Ff) sbias[tid] = 3.0f * bias[tid];

    float acc[3][4][4];
#pragma unroll
    for (int mt = 0; mt < 3; mt++)
#pragma unroll
        for (int nt = 0; nt < 4; nt++)
#pragma unroll
            for (int k = 0; k < 4; k++) acc[mt][nt][k] = 0.f;

    const char* xblk = reinterpret_cast<const char*>(
        g_xt + ((size_t)((n * Ll + l) * Dd) + d) * (HW24 * Cc));
    const char* xsl = xblk + (size_t)(wid * 48 + g) * 64 + tig * 16;
    const char* wb  = reinterpret_cast<const char*>(g_w2) + g * 64 + tig * 16;

#pragma unroll 1
    for (int p = 0; p < 9; ++p) {
        // prefetch next plane (A: 288 lines, B: 144 lines)
        if (p + 1 < 9) {
            const size_t poff = (size_t)(((p + 1) / 3) * Dd + ((p + 1) % 3)) * (HW24 * 64);
            const char* wnext = reinterpret_cast<const char*>(g_w2) + (size_t)(p + 1) * 18432;
            if (tid < 288) {
                pf_l1(xblk + poff + (size_t)tid * 128);
                if (tid < 144) pf_l1(wnext + (size_t)tid * 128);
            }
        }

        const char* xp = xsl + (size_t)((p / 3) * Dd + (p % 3)) * (HW24 * 64);
        const char* wp = wb + (size_t)p * 18432;

#pragma unroll
        for (int tap = 0; tap < 9; ++tap) {
            const int off = (tap / 3) * 24 + (tap % 3);
            uint4 bf[4];
#pragma unroll
            for (int nt = 0; nt < 4; nt++)
                bf[nt] = ldg128(wp + tap * 2048 + nt * 512);
#pragma unroll
            for (int mt = 0; mt < 3; mt++) {
                const uint4 a0 = ldg128(xp + (mt * 16 + off) * 64);
                const uint4 a1 = ldg128(xp + (mt * 16 + 8 + off) * 64);
#pragma unroll
                for (int nt = 0; nt < 4; nt++) {
                    mma_tf32(acc[mt][nt], a0.x, a1.x, a0.y, a1.y, bf[nt].x, bf[nt].y);
                    mma_tf32(acc[mt][nt], a0.z, a1.z, a0.w, a1.w, bf[nt].z, bf[nt].w);
                }
            }
        }
    }

    // ---- epilogue: per-warp smem staging for coalesced stores ----
    float* st = stg + wid * STAGE_F;
    const int sl = lane & 15;
    const int fh = lane >> 4;

#pragma unroll 1
    for (int mt = 0; mt < 3; mt++) {
#pragma unroll
        for (int nt = 0; nt < 4; nt++) {
            const int col = nt * 8 + 2 * tig;
            st[g * 33 + col]           = acc[mt][nt][0];
            st[g * 33 + col + 1]       = acc[mt][nt][1];
            st[(g + 8) * 33 + col]     = acc[mt][nt][2];
            st[(g + 8) * 33 + col + 1] = acc[mt][nt][3];
        }
        __syncwarp();
        const int s  = wid * 48 + mt * 16 + sl;     // 0..527, oh always < 22
        const int oh = s / 24;
        const int ow = s - oh * 24;
        if (ow < OE) {
            const size_t base = ((((size_t)n * Ff) * OL + l) * OD + d) * (OE * OE)
                                + (size_t)oh * OE + ow;
            const size_t fstr = (size_t)OL * OD * OE * OE;
#pragma unroll
            for (int fp = 0; fp < 16; fp++) {
                const int f = fp * 2 + fh;
                out[base + (size_t)f * fstr] = st[sl * 33 + f] + sbias[f];
            }
        }
        __syncwarp();
    }
}

// ---------------- launch ----------------
extern "C" void kernel_launch(void* const* d_in, const int* in_sizes, int n_in,
                              void* d_out, int out_size) {
    const float* x  = (const float*)d_in[0];
    const float* Wt = (const float*)d_in[1];
    const float* b  = (const float*)d_in[2];
    float* out = (float*)d_out;

    prep_all<<<Nn * Ll * Dd + 1, 256>>>(x, Wt);
    conv4d_mma<<<Nn * OL * OD, NT>>>(b, out);
}